// round 12
// baseline (speedup 1.0000x reference)
#include <cuda_runtime.h>
#include <cuda_bf16.h>

#define B_   64
#define S_   512
#define D_   1024
#define H_   1024
#define C_   1000
#define NBLK 128   // persistent scan CTAs (1 CTA/SM via smem, <=148 SMs)

// ---- device scratch (alloc-free rule: __device__ globals) ----
__device__ float    g_xe[B_ * S_ * D_];
__device__ float    g_xf[B_ * S_ * H_];
__device__ float    g_xi[B_ * S_ * H_];
__device__ float    g_h[2 * B_ * H_];     // fp32 hidden state, double buffered
__device__ unsigned g_htf[2 * B_ * H_];   // tf32-packed copy of h
__device__ unsigned g_count;              // grid barrier counter

__device__ __forceinline__ unsigned f2tf(float f) {
    unsigned u;
    asm("cvt.rna.tf32.f32 %0, %1;" : "=r"(u) : "f"(f));
    return u;
}

// D(16x8) += A(16x8 tf32, row) * B(8x8 tf32, col), fp32 accum
__device__ __forceinline__ void mma_tf32(float* c, const unsigned* a, const unsigned* b) {
    asm volatile(
        "mma.sync.aligned.m16n8k8.row.col.f32.tf32.tf32.f32 "
        "{%0,%1,%2,%3},{%4,%5,%6,%7},{%8,%9},{%0,%1,%2,%3};\n"
        : "+f"(c[0]), "+f"(c[1]), "+f"(c[2]), "+f"(c[3])
        : "r"(a[0]), "r"(a[1]), "r"(a[2]), "r"(a[3]), "r"(b[0]), "r"(b[1]));
}

// ---- K1: embedding gather + state/barrier init -------------------------------
__global__ void gather_kernel(const int* __restrict__ x, const float* __restrict__ emb) {
    int i = blockIdx.x * 256 + threadIdx.x;           // float4 index, B*S*D/4 total
    int tok = __ldg(&x[i >> 8]);                      // 256 float4 per (b,s) row
    ((float4*)g_xe)[i] = __ldg(&((const float4*)emb)[tok * 256 + (i & 255)]);
    if (i < (B_ * H_) / 4) {
        ((float4*)g_h)[i] = make_float4(0.f, 0.f, 0.f, 0.f);
        ((uint4*)g_htf)[i] = make_uint4(0u, 0u, 0u, 0u);  // tf32(0)=0
    }
    if (i == 0) g_count = 0u;
}

// ---- K2: prepass GEMMs  xf/xi = xe @ W^T + b  (TF32 mma, 128x128x32 tiles) ---
__global__ __launch_bounds__(256) void prepass_kernel(
    const float* __restrict__ Wf, const float* __restrict__ Wfb,
    const float* __restrict__ Wi, const float* __restrict__ Wib) {
    __shared__ unsigned As[128 * 36];   // stride 36 == 4 mod 32: conflict-free frags
    __shared__ unsigned Bs[128 * 36];

    int tid  = threadIdx.x;
    int n0g  = blockIdx.x * 128;                    // 0..2047 over both gates
    int gate = n0g >> 10;
    const float* W    = gate ? Wi  : Wf;
    const float* bias = gate ? Wib : Wfb;
    float*       out  = gate ? g_xi : g_xf;
    int n0 = n0g & 1023;
    int m0 = blockIdx.y * 128;

    int lane = tid & 31, warp = tid >> 5;
    int g = lane >> 2, tt = lane & 3;
    int wm = warp >> 2, wn = warp & 3;              // 2x4 warps -> 64x32 per warp

    float acc[4][4][4];
#pragma unroll
    for (int a = 0; a < 4; a++)
#pragma unroll
        for (int b = 0; b < 4; b++)
#pragma unroll
            for (int c = 0; c < 4; c++) acc[a][b][c] = 0.f;

    int srow = tid >> 3, sc4 = tid & 7;

    for (int kc = 0; kc < 32; kc++) {
        int kb = kc * 32;
        __syncthreads();
#pragma unroll
        for (int p = 0; p < 4; p++) {
            int r = srow + p * 32;
            float4 av = __ldg((const float4*)&g_xe[(m0 + r) * 1024 + kb + sc4 * 4]);
            *(uint4*)&As[r * 36 + sc4 * 4] =
                make_uint4(f2tf(av.x), f2tf(av.y), f2tf(av.z), f2tf(av.w));
            float4 bv = __ldg((const float4*)&W[(n0 + r) * 1024 + kb + sc4 * 4]);
            *(uint4*)&Bs[r * 36 + sc4 * 4] =
                make_uint4(f2tf(bv.x), f2tf(bv.y), f2tf(bv.z), f2tf(bv.w));
        }
        __syncthreads();
#pragma unroll
        for (int ks = 0; ks < 4; ks++) {
            int k0 = ks * 8;
            unsigned afr[4][4], bfr[4][2];
#pragma unroll
            for (int mt = 0; mt < 4; mt++) {
                int r = wm * 64 + mt * 16 + g;
                afr[mt][0] = As[r * 36 + k0 + tt];
                afr[mt][1] = As[(r + 8) * 36 + k0 + tt];
                afr[mt][2] = As[r * 36 + k0 + tt + 4];
                afr[mt][3] = As[(r + 8) * 36 + k0 + tt + 4];
            }
#pragma unroll
            for (int nt = 0; nt < 4; nt++) {
                int r = wn * 32 + nt * 8 + g;
                bfr[nt][0] = Bs[r * 36 + k0 + tt];
                bfr[nt][1] = Bs[r * 36 + k0 + tt + 4];
            }
#pragma unroll
            for (int mt = 0; mt < 4; mt++)
#pragma unroll
                for (int nt = 0; nt < 4; nt++) mma_tf32(acc[mt][nt], afr[mt], bfr[nt]);
        }
    }
#pragma unroll
    for (int mt = 0; mt < 4; mt++) {
        int r0 = m0 + wm * 64 + mt * 16 + g;
#pragma unroll
        for (int nt = 0; nt < 4; nt++) {
            int col = n0 + wn * 32 + nt * 8 + tt * 2;
            float b0 = __ldg(&bias[col]), b1 = __ldg(&bias[col + 1]);
            *(float2*)&out[r0 * 1024 + col] =
                make_float2(acc[mt][nt][0] + b0, acc[mt][nt][1] + b1);
            *(float2*)&out[(r0 + 8) * 1024 + col] =
                make_float2(acc[mt][nt][2] + b0, acc[mt][nt][3] + b1);
        }
    }
}

// ---- K3: persistent recurrent scan ------------------------------------------
// 128 CTAs x 256 thr. CTA owns 8 hidden cols; U slices resident in SMEM (tf32).
// warp = (mtile 0..3 [16 rows], khalf 0..1 [512 K]); per-khalf k-chunk staging.
#define SCAN_SMEM_WORDS (2*8*1028 + 2*64*132 + 2048)
#define SCAN_SMEM_BYTES (SCAN_SMEM_WORDS * 4)

__global__ __launch_bounds__(256) void scan_kernel(const float* __restrict__ Uf,
                                                   const float* __restrict__ Ui) {
    extern __shared__ unsigned sm[];
    unsigned* Ufs = sm;                    // [8][1028] tf32
    unsigned* Uis = sm + 8224;             // [8][1028]
    unsigned* HsA = sm + 16448;            // [64][132] khalf 0 chunk
    unsigned* HsB = sm + 24896;            // [64][132] khalf 1 chunk
    float*    Pre = (float*)(sm + 33344);  // [kh2][gate2][64][8]

    int tid = threadIdx.x, lane = tid & 31, wid = tid >> 5;
    int g = lane >> 2, tt = lane & 3;
    int mt = wid & 3, kh = wid >> 2;
    int c0 = blockIdx.x * 8;

    // preload + tf32-convert U slices (resident all 512 steps)
#pragma unroll
    for (int p = 0; p < 16; p++) {
        int idx = tid + p * 256;
        int gate = idx >> 11;
        int i = idx & 2047;
        int r = i >> 8, c4 = i & 255;
        const float* U = gate ? Ui : Uf;
        unsigned* Us = gate ? Uis : Ufs;
        float4 u = __ldg((const float4*)&U[(c0 + r) * 1024 + c4 * 4]);
        *(uint4*)&Us[r * 1028 + c4 * 4] =
            make_uint4(f2tf(u.x), f2tf(u.y), f2tf(u.z), f2tf(u.w));
    }
    __syncthreads();

    const unsigned* Hb = kh ? HsB : HsA;
    int srow = tid >> 5, sc4 = tid & 31;   // rows: srow + p*8, p in [0,8) -> 0..63

    for (int t = 0; t < 512; t++) {
        const unsigned* curtf = g_htf + (t & 1) * (B_ * H_);
        const float*    cur   = g_h   + (t & 1) * (B_ * H_);
        float*          nxt   = g_h   + ((t & 1) ^ 1) * (B_ * H_);
        unsigned*       nxttf = g_htf + ((t & 1) ^ 1) * (B_ * H_);

        float af[4] = {0.f, 0.f, 0.f, 0.f}, ai[4] = {0.f, 0.f, 0.f, 0.f};

        // prefetch chunk 0 (.cg: h changes across steps; L1 would be stale).
        // 8 uint4 per buffer per thread: 256 thr * 8 = 2048 uint4 = 64 rows x 128 words
        uint4 ra[8], rb[8];
#pragma unroll
        for (int p = 0; p < 8; p++) {
            int row = srow + p * 8;
            ra[p] = __ldcg((const uint4*)curtf + row * 256 + sc4);
            rb[p] = __ldcg((const uint4*)curtf + row * 256 + 128 + sc4);
        }
        for (int c = 0; c < 4; c++) {
            __syncthreads();                       // Hs free
#pragma unroll
            for (int p = 0; p < 8; p++) {
                int row = srow + p * 8;
                *(uint4*)&HsA[row * 132 + sc4 * 4] = ra[p];
                *(uint4*)&HsB[row * 132 + sc4 * 4] = rb[p];
            }
            if (c < 3) {
#pragma unroll
                for (int p = 0; p < 8; p++) {
                    int row = srow + p * 8;
                    ra[p] = __ldcg((const uint4*)curtf + row * 256 + (c + 1) * 32 + sc4);
                    rb[p] = __ldcg((const uint4*)curtf + row * 256 + 128 + (c + 1) * 32 + sc4);
                }
            }
            __syncthreads();
            // compute: 16 k-steps of m16n8k8 for both gates
#pragma unroll
            for (int s = 0; s < 16; s++) {
                int kk = s * 8;
                unsigned a[4], bf0[2], bi0[2];
                a[0] = Hb[(mt * 16 + g) * 132 + kk + tt];
                a[1] = Hb[(mt * 16 + 8 + g) * 132 + kk + tt];
                a[2] = Hb[(mt * 16 + g) * 132 + kk + tt + 4];
                a[3] = Hb[(mt * 16 + 8 + g) * 132 + kk + tt + 4];
                int ku = kh * 512 + c * 128 + kk + tt;
                bf0[0] = Ufs[g * 1028 + ku];
                bf0[1] = Ufs[g * 1028 + ku + 4];
                bi0[0] = Uis[g * 1028 + ku];
                bi0[1] = Uis[g * 1028 + ku + 4];
                mma_tf32(af, a, bf0);
                mma_tf32(ai, a, bi0);
            }
        }
        // store partial preactivations: Pre[(kh*2+gate)*64 + row][col]
        {
            int pf0 = ((kh * 2 + 0) * 64 + mt * 16 + g) * 8 + 2 * tt;
            Pre[pf0] = af[0];  Pre[pf0 + 1] = af[1];
            Pre[pf0 + 64] = af[2];  Pre[pf0 + 65] = af[3];
            int pi0 = ((kh * 2 + 1) * 64 + mt * 16 + g) * 8 + 2 * tt;
            Pre[pi0] = ai[0];  Pre[pi0 + 1] = ai[1];
            Pre[pi0 + 64] = ai[2];  Pre[pi0 + 65] = ai[3];
        }
        __syncthreads();
        // combine: h_new = sig(pf)*h + sig(pi)*xe ; 2 elements per thread
#pragma unroll
        for (int e2 = 0; e2 < 2; e2++) {
            int e = tid * 2 + e2;
            int b = e >> 3, j = e & 7;
            int src = (b * 512 + t) * 1024 + c0 + j;
            float pf = Pre[(b) * 8 + j] + Pre[(128 + b) * 8 + j] + __ldg(&g_xf[src]);
            float pi = Pre[(64 + b) * 8 + j] + Pre[(192 + b) * 8 + j] + __ldg(&g_xi[src]);
            float fo = 1.f / (1.f + expf(-pf));
            float io = 1.f / (1.f + expf(-pi));
            float hn = fo * __ldcg(&cur[b * 1024 + c0 + j]) + io * __ldg(&g_xe[src]);
            nxt[b * 1024 + c0 + j] = hn;
            nxttf[b * 1024 + c0 + j] = f2tf(hn);
        }
        // grid barrier (release stores, acquire spin)
        __syncthreads();
        if (tid == 0) {
            __threadfence();
            atomicAdd(&g_count, 1u);
            unsigned target = (unsigned)NBLK * (t + 1), v;
            do {
                asm volatile("ld.acquire.gpu.u32 %0, [%1];"
                             : "=r"(v) : "l"(&g_count) : "memory");
            } while (v < target);
        }
        __syncthreads();
    }
}

// ---- K4: classifier  out = h_last @ fc_w^T + fc_b ----------------------------
__global__ void fc_kernel(const float* __restrict__ fc_w, const float* __restrict__ fc_b,
                          float* __restrict__ out) {
    int c = blockIdx.x, b = threadIdx.x;
    const float4* hv = (const float4*)&g_h[b * 1024];   // final h in buffer 0
    const float4* wv = (const float4*)&fc_w[c * 1024];
    float a0 = 0.f, a1 = 0.f, a2 = 0.f, a3 = 0.f;
#pragma unroll 8
    for (int k = 0; k < 256; k++) {
        float4 h4 = hv[k];
        float4 w4 = __ldg(&wv[k]);
        a0 += h4.x * w4.x; a1 += h4.y * w4.y;
        a2 += h4.z * w4.z; a3 += h4.w * w4.w;
    }
    out[b * 1000 + c] = (a0 + a1) + (a2 + a3) + __ldg(&fc_b[c]);
}

// ---- launch ------------------------------------------------------------------
extern "C" void kernel_launch(void* const* d_in, const int* in_sizes, int n_in,
                              void* d_out, int out_size) {
    const int*   x    = (const int*)d_in[0];
    const float* emb  = (const float*)d_in[1];
    const float* Wf_w = (const float*)d_in[2];
    const float* Wf_b = (const float*)d_in[3];
    const float* Uf_w = (const float*)d_in[4];
    const float* Wi_w = (const float*)d_in[5];
    const float* Wi_b = (const float*)d_in[6];
    const float* Ui_w = (const float*)d_in[7];
    const float* fc_w = (const float*)d_in[8];
    const float* fc_b = (const float*)d_in[9];
    float* out = (float*)d_out;

    cudaFuncSetAttribute(scan_kernel, cudaFuncAttributeMaxDynamicSharedMemorySize,
                         SCAN_SMEM_BYTES);

    gather_kernel<<<(B_ * S_ * D_ / 4) / 256, 256>>>(x, emb);
    prepass_kernel<<<dim3(16, 256), 256>>>(Wf_w, Wf_b, Wi_w, Wi_b);
    scan_kernel<<<NBLK, 256, SCAN_SMEM_BYTES>>>(Uf_w, Ui_w);
    fc_kernel<<<C_, B_>>>(fc_w, fc_b, out);
}

// round 15
// speedup vs baseline: 1.3144x; 1.3144x over previous
#include <cuda_runtime.h>
#include <cuda_bf16.h>
#include <cuda_fp16.h>

#define B_   64
#define S_   512
#define D_   1024
#define H_   1024
#define C_   1000
#define NBLK 128   // persistent scan CTAs, 1/SM

// ---- device scratch (alloc-free rule: __device__ globals) ----
__device__ float    g_xe[B_ * S_ * D_];
__device__ float    g_xf[B_ * S_ * H_];
__device__ float    g_xi[B_ * S_ * H_];
__device__ float    g_h[B_ * H_];          // final h (fp32) for fc
__device__ unsigned g_hh[2 * (B_ * H_ / 2)];  // h in fp16, fragment-quad layout, dbl buf
__device__ unsigned g_count;               // grid barrier counter

__device__ __forceinline__ unsigned pack_h2(float a, float b) {
    __half2 h = __floats2half2_rn(a, b);
    return *(unsigned*)&h;
}

// D(16x8) += A(16x16 f16, row) * B(16x8 f16, col), fp32 accum
__device__ __forceinline__ void mma_f16(float* c, const unsigned* a, const unsigned* b) {
    asm volatile(
        "mma.sync.aligned.m16n8k16.row.col.f32.f16.f16.f32 "
        "{%0,%1,%2,%3},{%4,%5,%6,%7},{%8,%9},{%0,%1,%2,%3};\n"
        : "+f"(c[0]), "+f"(c[1]), "+f"(c[2]), "+f"(c[3])
        : "r"(a[0]), "r"(a[1]), "r"(a[2]), "r"(a[3]), "r"(b[0]), "r"(b[1]));
}

// ---- K1: embedding gather + state/barrier init -------------------------------
__global__ void gather_kernel(const int* __restrict__ x, const float* __restrict__ emb) {
    int i = blockIdx.x * 256 + threadIdx.x;           // float4 index, B*S*D/4 total
    int tok = __ldg(&x[i >> 8]);                      // 256 float4 per (b,s) row
    ((float4*)g_xe)[i] = __ldg(&((const float4*)emb)[tok * 256 + (i & 255)]);
    if (i < 8192)                                     // zero h buffer 0 (32768 words)
        ((uint4*)g_hh)[i] = make_uint4(0u, 0u, 0u, 0u);
    if (i == 0) g_count = 0u;
}

// ---- K2: prepass GEMMs  xf/xi = xe @ W^T + b  (fp16 mma, 128x128x32 tiles) ---
__global__ __launch_bounds__(256) void prepass_kernel(
    const float* __restrict__ Wf, const float* __restrict__ Wfb,
    const float* __restrict__ Wi, const float* __restrict__ Wib) {
    __shared__ unsigned As[128 * 20];   // half2 words; row stride 20 (== 4 mod 32)
    __shared__ unsigned Bs[128 * 20];

    int tid  = threadIdx.x;
    int n0g  = blockIdx.x * 128;                    // 0..2047 over both gates
    int gate = n0g >> 10;
    const float* W    = gate ? Wi  : Wf;
    const float* bias = gate ? Wib : Wfb;
    float*       out  = gate ? g_xi : g_xf;
    int n0 = n0g & 1023;
    int m0 = blockIdx.y * 128;

    int lane = tid & 31, warp = tid >> 5;
    int g = lane >> 2, tt = lane & 3;
    int wm = warp >> 2, wn = warp & 3;              // 2x4 warps -> 64x32 per warp

    float acc[4][4][4];
#pragma unroll
    for (int a = 0; a < 4; a++)
#pragma unroll
        for (int b = 0; b < 4; b++)
#pragma unroll
            for (int c = 0; c < 4; c++) acc[a][b][c] = 0.f;

    for (int kc = 0; kc < 32; kc++) {
        int kb = kc * 32;
        __syncthreads();
#pragma unroll
        for (int p = 0; p < 4; p++) {
            int idx = tid + p * 256;                 // 0..1023 float4 slots
            int r = idx >> 3, f4 = idx & 7;
            float4 av = __ldg((const float4*)&g_xe[(m0 + r) * 1024 + kb + f4 * 4]);
            As[r * 20 + f4 * 2]     = pack_h2(av.x, av.y);
            As[r * 20 + f4 * 2 + 1] = pack_h2(av.z, av.w);
            float4 bv = __ldg((const float4*)&W[(n0 + r) * 1024 + kb + f4 * 4]);
            Bs[r * 20 + f4 * 2]     = pack_h2(bv.x, bv.y);
            Bs[r * 20 + f4 * 2 + 1] = pack_h2(bv.z, bv.w);
        }
        __syncthreads();
#pragma unroll
        for (int ks = 0; ks < 2; ks++) {             // two k16 steps per 32-chunk
            int k0 = ks * 8;
            unsigned afr[4][4], bfr[4][2];
#pragma unroll
            for (int mt = 0; mt < 4; mt++) {
                int r = wm * 64 + mt * 16 + g;
                afr[mt][0] = As[r * 20 + k0 + tt];
                afr[mt][1] = As[(r + 8) * 20 + k0 + tt];
                afr[mt][2] = As[r * 20 + k0 + tt + 4];
                afr[mt][3] = As[(r + 8) * 20 + k0 + tt + 4];
            }
#pragma unroll
            for (int nt = 0; nt < 4; nt++) {
                int r = wn * 32 + nt * 8 + g;
                bfr[nt][0] = Bs[r * 20 + k0 + tt];
                bfr[nt][1] = Bs[r * 20 + k0 + tt + 4];
            }
#pragma unroll
            for (int mt = 0; mt < 4; mt++)
#pragma unroll
                for (int nt = 0; nt < 4; nt++) mma_f16(acc[mt][nt], afr[mt], bfr[nt]);
        }
    }
#pragma unroll
    for (int mt = 0; mt < 4; mt++) {
        int r0 = m0 + wm * 64 + mt * 16 + g;
#pragma unroll
        for (int nt = 0; nt < 4; nt++) {
            int col = n0 + wn * 32 + nt * 8 + tt * 2;
            float b0 = __ldg(&bias[col]), b1 = __ldg(&bias[col + 1]);
            *(float2*)&out[r0 * 1024 + col] =
                make_float2(acc[mt][nt][0] + b0, acc[mt][nt][1] + b1);
            *(float2*)&out[(r0 + 8) * 1024 + col] =
                make_float2(acc[mt][nt][2] + b0, acc[mt][nt][3] + b1);
        }
    }
}

// ---- K3: persistent recurrent scan ------------------------------------------
// 128 CTAs x 256 thr. CTA owns 8 cols. warp = k-slice of 128 (kh 0..7).
// U fragments live in REGISTERS (loaded once). h fragments come straight from
// global memory in a fragment-quad fp16 layout (no SMEM staging at all).
__global__ __launch_bounds__(256) void scan_kernel(const float* __restrict__ Uf,
                                                   const float* __restrict__ Ui) {
    __shared__ float Pre[16 * 512];        // [kh 8][gate 2][64 rows][8 cols]

    int tid = threadIdx.x, lane = tid & 31;
    int kh = tid >> 5;                     // warp = k-slice
    int g = lane >> 2, tt = lane & 3;
    int c0 = blockIdx.x * 8;

    // --- preload U fragments into registers (constant over t) ---
    // B-frag (col-major): b0 = {U[c0+g][k..k+1]}, b1 = {U[c0+g][k+8..k+9]}
    unsigned Bf[8][2], Bi2[8][2];
#pragma unroll
    for (int s = 0; s < 8; s++) {
        int k0 = kh * 128 + s * 16 + 2 * tt;
        const float* uf = &Uf[(c0 + g) * 1024 + k0];
        const float* ui = &Ui[(c0 + g) * 1024 + k0];
        Bf[s][0]  = pack_h2(__ldg(uf),     __ldg(uf + 1));
        Bf[s][1]  = pack_h2(__ldg(uf + 8), __ldg(uf + 9));
        Bi2[s][0] = pack_h2(__ldg(ui),     __ldg(ui + 1));
        Bi2[s][1] = pack_h2(__ldg(ui + 8), __ldg(ui + 9));
    }

    // --- combine-phase constants (thread owns elems e = 2*tid, 2*tid+1) ---
    int bq = tid >> 2;                     // batch row of owned elems
    int j0 = (tid * 2) & 7;                // even col within CTA's 8
    // fp16 quad store slot for (bq, c0+j0..j0+1):
    unsigned wofs = ((((unsigned)(blockIdx.x >> 1) * 4 + (bq >> 4)) * 32
                      + (bq & 7) * 4 + (tid & 3)) * 4)
                    + (blockIdx.x & 1) * 2 + ((bq >> 3) & 1);
    float hreg[2] = {0.f, 0.f};

    const uint4* qp = (const uint4*)g_hh;  // 2 x 8192 uint4 buffers
    unsigned qb0 = kh * 1024u + g * 4u + tt;

    for (int t = 0; t < 512; t++) {
        // prefetch combine inputs (independent of h)
        int src = (bq * 512 + t) * 1024 + c0 + j0;
        float2 cxf = __ldg((const float2*)&g_xf[src]);
        float2 cxi = __ldg((const float2*)&g_xi[src]);
        float2 cxe = __ldg((const float2*)&g_xe[src]);

        float af[4][4], ai[4][4];
#pragma unroll
        for (int a = 0; a < 4; a++)
#pragma unroll
            for (int c = 0; c < 4; c++) { af[a][c] = 0.f; ai[a][c] = 0.f; }

        unsigned qbase = (t & 1) * 8192u + qb0;
        uint4 q[8], qn[8];
#pragma unroll
        for (int p = 0; p < 8; p++) q[p] = __ldcg(qp + qbase + p * 32);
#pragma unroll
        for (int grp = 0; grp < 4; grp++) {
            if (grp < 3) {
#pragma unroll
                for (int p = 0; p < 8; p++)
                    qn[p] = __ldcg(qp + qbase + (grp + 1) * 256 + p * 32);
            }
#pragma unroll
            for (int p = 0; p < 8; p++) {
                int j = grp * 8 + p;
                int s = j >> 2, mt = j & 3;
                mma_f16(af[mt], (const unsigned*)&q[p], Bf[s]);
                mma_f16(ai[mt], (const unsigned*)&q[p], Bi2[s]);
            }
#pragma unroll
            for (int p = 0; p < 8; p++) q[p] = qn[p];
        }

        // store partial preactivations
        int pb = kh * 1024;
#pragma unroll
        for (int mt = 0; mt < 4; mt++) {
            int i0 = pb + (mt * 16 + g) * 8 + 2 * tt;
            Pre[i0]      = af[mt][0];  Pre[i0 + 1]  = af[mt][1];
            Pre[i0 + 64] = af[mt][2];  Pre[i0 + 65] = af[mt][3];
            int i1 = i0 + 512;
            Pre[i1]      = ai[mt][0];  Pre[i1 + 1]  = ai[mt][1];
            Pre[i1 + 64] = ai[mt][2];  Pre[i1 + 65] = ai[mt][3];
        }
        __syncthreads();

        // combine: reduce 8 k-slices, gate, update h
        float hn[2];
        float cf[2] = {cxf.x, cxf.y}, ci[2] = {cxi.x, cxi.y}, ce[2] = {cxe.x, cxe.y};
#pragma unroll
        for (int e2 = 0; e2 < 2; e2++) {
            int e = tid * 2 + e2;
            float pf = cf[e2], pi = ci[e2];
#pragma unroll
            for (int k8 = 0; k8 < 8; k8++) {
                pf += Pre[k8 * 1024 + e];
                pi += Pre[k8 * 1024 + 512 + e];
            }
            float fo = 1.f / (1.f + __expf(-pf));
            float io = 1.f / (1.f + __expf(-pi));
            hn[e2] = fo * hreg[e2] + io * ce[e2];
            hreg[e2] = hn[e2];
        }
        g_hh[((t & 1) ^ 1) * 32768u + wofs] = pack_h2(hn[0], hn[1]);
        if (t == 511) {
            g_h[bq * 1024 + c0 + j0]     = hn[0];
            g_h[bq * 1024 + c0 + j0 + 1] = hn[1];
        }
        __syncthreads();

        if (t < 511) {
            if (tid == 0) {
                __threadfence();
                asm volatile("red.release.gpu.global.add.u32 [%0], %1;"
                             :: "l"(&g_count), "r"(1u) : "memory");
                unsigned target = (unsigned)NBLK * (t + 1), v;
                do {
                    asm volatile("ld.acquire.gpu.u32 %0, [%1];"
                                 : "=r"(v) : "l"(&g_count) : "memory");
                } while (v < target);
            }
            __syncthreads();
        }
    }
}

// ---- K4: classifier  out = h_last @ fc_w^T + fc_b ----------------------------
// 125 blocks x 256 thr; thread = (batch, 2 classes). h reuse within block.
__global__ __launch_bounds__(256) void fc_kernel(const float* __restrict__ fc_w,
                                                 const float* __restrict__ fc_b,
                                                 float* __restrict__ out) {
    int tid = threadIdx.x;
    int b = tid & 63, cg = tid >> 6;
    int c = blockIdx.x * 8 + cg * 2;
    const float4* hv = (const float4*)&g_h[b * 1024];
    const float4* w0 = (const float4*)&fc_w[c * 1024];
    const float4* w1 = (const float4*)&fc_w[(c + 1) * 1024];
    float a0 = 0.f, a1 = 0.f, b0 = 0.f, b1 = 0.f;
#pragma unroll 4
    for (int k = 0; k < 256; k++) {
        float4 h4 = hv[k];
        float4 x0 = __ldg(w0 + k);
        float4 x1 = __ldg(w1 + k);
        a0 += h4.x * x0.x + h4.y * x0.y;  a1 += h4.z * x0.z + h4.w * x0.w;
        b0 += h4.x * x1.x + h4.y * x1.y;  b1 += h4.z * x1.z + h4.w * x1.w;
    }
    out[b * 1000 + c]     = a0 + a1 + __ldg(&fc_b[c]);
    out[b * 1000 + c + 1] = b0 + b1 + __ldg(&fc_b[c + 1]);
}

// ---- launch ------------------------------------------------------------------
extern "C" void kernel_launch(void* const* d_in, const int* in_sizes, int n_in,
                              void* d_out, int out_size) {
    const int*   x    = (const int*)d_in[0];
    const float* emb  = (const float*)d_in[1];
    const float* Wf_w = (const float*)d_in[2];
    const float* Wf_b = (const float*)d_in[3];
    const float* Uf_w = (const float*)d_in[4];
    const float* Wi_w = (const float*)d_in[5];
    const float* Wi_b = (const float*)d_in[6];
    const float* Ui_w = (const float*)d_in[7];
    const float* fc_w = (const float*)d_in[8];
    const float* fc_b = (const float*)d_in[9];
    float* out = (float*)d_out;

    gather_kernel<<<(B_ * S_ * D_ / 4) / 256, 256>>>(x, emb);
    prepass_kernel<<<dim3(16, 256), 256>>>(Wf_w, Wf_b, Wi_w, Wi_b);
    scan_kernel<<<NBLK, 256>>>(Uf_w, Ui_w);
    fc_kernel<<<125, 256>>>(fc_w, fc_b, out);
}